// round 2
// baseline (speedup 1.0000x reference)
#include <cuda_runtime.h>

#define NN  100000
#define EE  3200000
#define NB_SCAN 391   // ceil(NN/256)

// ---------------- scratch (static device globals; no runtime allocation) ----
__device__ int   g_degi[NN];
__device__ float g_dinv[NN];
__device__ int   g_src[EE];
__device__ int   g_dst[EE];
__device__ int   g_off[NN + 1];
__device__ int   g_cur[NN];
__device__ int   g_csrc[EE];
__device__ float g_h1s[NN * 32];    // dinv[n] * (x[n] @ init_w1), cols = k*16+h
__device__ float g_root1[NN * 32];  // x[n] @ root_w1
__device__ float g_hs[NN * 16];     // dinv[n] * h[n]
__device__ float g_aggh[NN * 16];   // dinv[d] * sum_src hs[src]
__device__ int   g_bsum[512];
__device__ int   g_boff[512];

// ---------------- K0: zero degree histogram ---------------------------------
__global__ void k_zero() {
    int i = blockIdx.x * blockDim.x + threadIdx.x;
    if (i < NN) g_degi[i] = 0;
}

// ---------------- K1: edge prep (int32 src/dst, degree histogram) -----------
// NOTE: edge_index is int32 (JAX default x64-disabled downcasts int64).
__global__ void k_edge_prep(const int* __restrict__ ei) {
    int e = blockIdx.x * blockDim.x + threadIdx.x;
    if (e >= EE) return;
    int s = ei[e];
    int d = ei[EE + e];
    g_src[e] = s;
    g_dst[e] = d;
    if ((unsigned)d < NN) atomicAdd(&g_degi[d], 1);
}

// ---------------- K2: dinv ---------------------------------------------------
__global__ void k_dinv() {
    int n = blockIdx.x * blockDim.x + threadIdx.x;
    if (n >= NN) return;
    int d = g_degi[n];
    g_dinv[n] = (d > 0) ? rsqrtf((float)d) : 0.0f;
}

// ---------------- K3/K4/K5: exclusive scan of degrees -> row offsets --------
__global__ void k_scan_part() {
    __shared__ int sm[256];
    int t = threadIdx.x, b = blockIdx.x;
    int n = b * 256 + t;
    sm[t] = (n < NN) ? g_degi[n] : 0;
    __syncthreads();
    for (int s = 128; s > 0; s >>= 1) {
        if (t < s) sm[t] += sm[t + s];
        __syncthreads();
    }
    if (t == 0) g_bsum[b] = sm[0];
}

__global__ void k_scan_top() {
    __shared__ int sm[512];
    int t = threadIdx.x;
    int v = (t < NB_SCAN) ? g_bsum[t] : 0;
    sm[t] = v;
    __syncthreads();
    for (int d = 1; d < 512; d <<= 1) {
        int x = (t >= d) ? sm[t - d] : 0;
        __syncthreads();
        sm[t] += x;
        __syncthreads();
    }
    if (t < NB_SCAN) g_boff[t] = sm[t] - v;  // exclusive
}

__global__ void k_scan_out() {
    __shared__ int sm[256];
    int t = threadIdx.x, b = blockIdx.x;
    int n = b * 256 + t;
    int v = (n < NN) ? g_degi[n] : 0;
    sm[t] = v;
    __syncthreads();
    for (int d = 1; d < 256; d <<= 1) {
        int x = (t >= d) ? sm[t - d] : 0;
        __syncthreads();
        sm[t] += x;
        __syncthreads();
    }
    int excl = sm[t] - v + g_boff[b];
    if (n < NN) {
        g_off[n] = excl;
        g_cur[n] = excl;
    }
    if (b == 0 && t == 0) g_off[NN] = EE;
}

// ---------------- K6: CSR scatter (src list grouped by dst) -----------------
__global__ void k_csr() {
    int e = blockIdx.x * blockDim.x + threadIdx.x;
    if (e >= EE) return;
    int d = g_dst[e];
    if ((unsigned)d >= NN) return;
    int pos = atomicAdd(&g_cur[d], 1);
    g_csrc[pos] = g_src[e];
}

// ---------------- K7: GEMM1  h1s = dinv*(x@Wi), root1 = x@Wr ----------------
// tile: 64 nodes x 64 outputs, 256 threads, thread = 4 nodes x 4 outputs
__global__ void __launch_bounds__(256) k_gemm1(const float* __restrict__ x,
                                               const float* __restrict__ wi,
                                               const float* __restrict__ wr) {
    __shared__ float xs[64 * 68];
    __shared__ float ws[64 * 64];
    int tid = threadIdx.x;
    int nb = blockIdx.x * 64;
    int co = tid & 15;   // output group: cols co*4 .. co*4+3
    int rn = tid >> 4;   // row group:    rows rn*4 .. rn*4+3

    float acc[4][4];
#pragma unroll
    for (int i = 0; i < 4; i++)
#pragma unroll
        for (int j = 0; j < 4; j++) acc[i][j] = 0.0f;

    for (int fc = 0; fc < 256; fc += 64) {
        // stage x tile [64 rows x 64 features]
#pragma unroll
        for (int j = 0; j < 4; j++) {
            int idx = tid + 256 * j;
            int r = idx >> 4;
            int c4 = (idx & 15) * 4;
            float4 v = make_float4(0.f, 0.f, 0.f, 0.f);
            int node = nb + r;
            if (node < NN) v = *(const float4*)&x[node * 256 + fc + c4];
            *(float4*)&xs[r * 68 + c4] = v;
        }
        // stage W tile [64 f x 64 outputs]; o<32 -> init, o>=32 -> root
#pragma unroll
        for (int j = 0; j < 16; j++) {
            int idx = tid + 256 * j;
            int fl = idx >> 6;
            int o = idx & 63;
            int oo = o & 31;
            const float* wp = (o < 32) ? wi : wr;
            ws[fl * 64 + o] = wp[(oo >> 4) * 4096 + (fc + fl) * 16 + (oo & 15)];
        }
        __syncthreads();
#pragma unroll 8
        for (int f = 0; f < 64; f++) {
            float4 w = *(float4*)&ws[f * 64 + co * 4];
#pragma unroll
            for (int i = 0; i < 4; i++) {
                float xv = xs[(rn * 4 + i) * 68 + f];
                acc[i][0] += xv * w.x;
                acc[i][1] += xv * w.y;
                acc[i][2] += xv * w.z;
                acc[i][3] += xv * w.w;
            }
        }
        __syncthreads();
    }
    // epilogue
#pragma unroll
    for (int i = 0; i < 4; i++) {
        int node = nb + rn * 4 + i;
        if (node >= NN) continue;
        float4 v = make_float4(acc[i][0], acc[i][1], acc[i][2], acc[i][3]);
        if (co < 8) {
            float dv = g_dinv[node];
            v.x *= dv; v.y *= dv; v.z *= dv; v.w *= dv;
            *(float4*)&g_h1s[node * 32 + co * 4] = v;
        } else {
            *(float4*)&g_root1[node * 32 + (co - 8) * 4] = v;
        }
    }
}

// ---------------- K8: layer-1 aggregate + combine (warp per dst node) -------
__global__ void __launch_bounds__(256) k_agg1(const float* __restrict__ bias1,
                                              float* __restrict__ out_agg) {
    int node = blockIdx.x * 8 + (threadIdx.x >> 5);
    int lane = threadIdx.x & 31;
    if (node >= NN) return;
    int beg = g_off[node], end = g_off[node + 1];
    float acc0 = 0.f, acc1 = 0.f;
    for (int t = beg; t < end; t += 32) {
        int idx = t + lane;
        int sv = (idx < end) ? g_csrc[idx] : 0;
        int cnt = min(32, end - t);
        int j = 0;
        for (; j + 4 <= cnt; j += 4) {
            int s0 = __shfl_sync(0xffffffffu, sv, j);
            int s1 = __shfl_sync(0xffffffffu, sv, j + 1);
            int s2 = __shfl_sync(0xffffffffu, sv, j + 2);
            int s3 = __shfl_sync(0xffffffffu, sv, j + 3);
            float a0 = g_h1s[s0 * 32 + lane];
            float a1 = g_h1s[s1 * 32 + lane];
            float a2 = g_h1s[s2 * 32 + lane];
            float a3 = g_h1s[s3 * 32 + lane];
            acc0 += a0 + a2;
            acc1 += a1 + a3;
        }
        for (; j < cnt; j++) {
            int s = __shfl_sync(0xffffffffu, sv, j);
            acc0 += g_h1s[s * 32 + lane];
        }
    }
    float dv = g_dinv[node];
    float v = dv * (acc0 + acc1) + g_root1[node * 32 + lane] + bias1[lane];
    float r = fmaxf(v, 0.0f);
    float other = __shfl_xor_sync(0xffffffffu, r, 16);
    float h = 0.5f * (r + other);       // mean over K (outer relu is identity)
    if (lane < 16) {
        out_agg[node * 16 + lane] = h;  // agg_feature output
        g_hs[node * 16 + lane] = h * dv;
    }
}

// ---------------- K9: layer-2 aggregate (warp per dst node, 2 nbrs/iter) ----
__global__ void __launch_bounds__(256) k_agg2() {
    int node = blockIdx.x * 8 + (threadIdx.x >> 5);
    int lane = threadIdx.x & 31;
    if (node >= NN) return;
    int f = lane & 15;
    int p = lane >> 4;
    int beg = g_off[node], end = g_off[node + 1];
    float acc = 0.f;
    for (int t = beg; t < end; t += 32) {
        int idx = t + lane;
        int sv = (idx < end) ? g_csrc[idx] : 0;
        int cnt = min(32, end - t);
        for (int j = 0; j < cnt; j += 2) {
            int s0 = __shfl_sync(0xffffffffu, sv, j);
            int s1 = (j + 1 < cnt) ? __shfl_sync(0xffffffffu, sv, j + 1) : -1;
            int s = p ? s1 : s0;
            if (s >= 0) acc += g_hs[s * 16 + f];
        }
    }
    acc += __shfl_xor_sync(0xffffffffu, acc, 16);
    if (lane < 16) g_aggh[node * 16 + lane] = acc * g_dinv[node];
}

// ---------------- K10: layer-2 transform + log_softmax (thread per node) ----
__global__ void __launch_bounds__(256) k_final(const float* __restrict__ wi2,
                                               const float* __restrict__ wr2,
                                               const float* __restrict__ b2,
                                               const float* __restrict__ hsrc,
                                               float* __restrict__ out_logits) {
    __shared__ float Wi[256], Wr[256], Ba[16];
    int t = threadIdx.x;
    // K-mean commutes with identity activation -> average weights over stacks
    Wi[t] = 0.5f * (wi2[t] + wi2[256 + t]);
    Wr[t] = 0.5f * (wr2[t] + wr2[256 + t]);
    if (t < 16) Ba[t] = 0.5f * (b2[t] + b2[16 + t]);
    __syncthreads();

    int n = blockIdx.x * 256 + t;
    if (n >= NN) return;
    float g[16], h[16];
#pragma unroll
    for (int j = 0; j < 4; j++) {
        float4 gv = *(const float4*)&g_aggh[n * 16 + j * 4];
        float4 hv = *(const float4*)&hsrc[n * 16 + j * 4];
        g[j * 4 + 0] = gv.x; g[j * 4 + 1] = gv.y; g[j * 4 + 2] = gv.z; g[j * 4 + 3] = gv.w;
        h[j * 4 + 0] = hv.x; h[j * 4 + 1] = hv.y; h[j * 4 + 2] = hv.z; h[j * 4 + 3] = hv.w;
    }
    float l[16];
    float m = -1e30f;
#pragma unroll
    for (int o = 0; o < 16; o++) {
        float a = Ba[o];
#pragma unroll
        for (int ff = 0; ff < 16; ff++)
            a += g[ff] * Wi[ff * 16 + o] + h[ff] * Wr[ff * 16 + o];
        l[o] = a;
        m = fmaxf(m, a);
    }
    float s = 0.f;
#pragma unroll
    for (int o = 0; o < 16; o++) s += expf(l[o] - m);
    float ls = logf(s);
#pragma unroll
    for (int j = 0; j < 4; j++) {
        float4 v;
        v.x = l[j * 4 + 0] - m - ls;
        v.y = l[j * 4 + 1] - m - ls;
        v.z = l[j * 4 + 2] - m - ls;
        v.w = l[j * 4 + 3] - m - ls;
        *(float4*)&out_logits[n * 16 + j * 4] = v;
    }
}

// ---------------- launch -----------------------------------------------------
extern "C" void kernel_launch(void* const* d_in, const int* in_sizes, int n_in,
                              void* d_out, int out_size) {
    const float* x   = (const float*)d_in[0];
    const int*   ei  = (const int*)d_in[1];     // int32! (JAX x64 disabled)
    const float* wi1 = (const float*)d_in[2];
    const float* wr1 = (const float*)d_in[3];
    const float* b1  = (const float*)d_in[4];
    const float* wi2 = (const float*)d_in[5];
    const float* wr2 = (const float*)d_in[6];
    const float* b2  = (const float*)d_in[7];
    float* out        = (float*)d_out;
    float* out_logits = out;            // [N, 16] log_softmax
    float* out_agg    = out + NN * 16;  // [N, 16] agg_feature

    k_zero<<<(NN + 255) / 256, 256>>>();
    k_edge_prep<<<(EE + 255) / 256, 256>>>(ei);
    k_dinv<<<(NN + 255) / 256, 256>>>();
    k_scan_part<<<NB_SCAN, 256>>>();
    k_scan_top<<<1, 512>>>();
    k_scan_out<<<NB_SCAN, 256>>>();
    k_csr<<<(EE + 255) / 256, 256>>>();
    k_gemm1<<<(NN + 63) / 64, 256>>>(x, wi1, wr1);
    k_agg1<<<(NN + 7) / 8, 256>>>(b1, out_agg);
    k_agg2<<<(NN + 7) / 8, 256>>>();
    k_final<<<(NN + 255) / 256, 256>>>(wi2, wr2, b2, out_agg, out_logits);
}

// round 3
// speedup vs baseline: 1.2221x; 1.2221x over previous
#include <cuda_runtime.h>

#define NN  100000
#define EE  3200000
#define NB_SCAN 391   // ceil(NN/256)

// ---------------- scratch (static device globals) ---------------------------
__device__ int   g_degi[NN];
__device__ float g_dinv[NN];
__device__ int   g_off[NN + 1];
__device__ int   g_cur[NN];
__device__ int   g_csrc[EE];
__device__ float g_h1s[NN * 32];    // dinv[n] * (x[n] @ init_w1), cols = k*16+h
__device__ float g_root1[NN * 32];  // x[n] @ root_w1
__device__ float g_hs[NN * 16];     // dinv[n] * h[n]
__device__ float g_aggh[NN * 16];   // dinv[d] * sum_src hs[src]
__device__ int   g_bsum[512];
__device__ int   g_boff[512];

// ---------------- packed f32x2 helpers ---------------------------------------
__device__ __forceinline__ unsigned long long ffma2(unsigned long long a,
                                                    unsigned long long b,
                                                    unsigned long long c) {
    unsigned long long d;
    asm("fma.rn.f32x2 %0, %1, %2, %3;" : "=l"(d) : "l"(a), "l"(b), "l"(c));
    return d;
}
__device__ __forceinline__ unsigned long long pack2(float lo, float hi) {
    unsigned long long r;
    asm("mov.b64 %0, {%1, %2};" : "=l"(r) : "f"(lo), "f"(hi));
    return r;
}
__device__ __forceinline__ void unpack2(unsigned long long v, float& lo, float& hi) {
    asm("mov.b64 {%0, %1}, %2;" : "=f"(lo), "=f"(hi) : "l"(v));
}

// ---------------- K0: zero degree histogram ---------------------------------
__global__ void k_zero() {
    int i = blockIdx.x * blockDim.x + threadIdx.x;
    if (i < NN) g_degi[i] = 0;
}

// ---------------- K1: degree histogram (int32 dst, int4 vectorized) ---------
__global__ void k_hist(const int* __restrict__ ei) {
    int e4 = blockIdx.x * blockDim.x + threadIdx.x;
    if (e4 >= EE / 4) return;
    int4 d = *(const int4*)&ei[EE + e4 * 4];
    if ((unsigned)d.x < NN) atomicAdd(&g_degi[d.x], 1);
    if ((unsigned)d.y < NN) atomicAdd(&g_degi[d.y], 1);
    if ((unsigned)d.z < NN) atomicAdd(&g_degi[d.z], 1);
    if ((unsigned)d.w < NN) atomicAdd(&g_degi[d.w], 1);
}

// ---------------- K2: scan partials + dinv -----------------------------------
__global__ void k_scan_part() {
    __shared__ int sm[256];
    int t = threadIdx.x, b = blockIdx.x;
    int n = b * 256 + t;
    int v = (n < NN) ? g_degi[n] : 0;
    if (n < NN) g_dinv[n] = (v > 0) ? rsqrtf((float)v) : 0.0f;
    sm[t] = v;
    __syncthreads();
    for (int s = 128; s > 0; s >>= 1) {
        if (t < s) sm[t] += sm[t + s];
        __syncthreads();
    }
    if (t == 0) g_bsum[b] = sm[0];
}

__global__ void k_scan_top() {
    __shared__ int sm[512];
    int t = threadIdx.x;
    int v = (t < NB_SCAN) ? g_bsum[t] : 0;
    sm[t] = v;
    __syncthreads();
    for (int d = 1; d < 512; d <<= 1) {
        int x = (t >= d) ? sm[t - d] : 0;
        __syncthreads();
        sm[t] += x;
        __syncthreads();
    }
    if (t < NB_SCAN) g_boff[t] = sm[t] - v;  // exclusive
}

__global__ void k_scan_out() {
    __shared__ int sm[256];
    int t = threadIdx.x, b = blockIdx.x;
    int n = b * 256 + t;
    int v = (n < NN) ? g_degi[n] : 0;
    sm[t] = v;
    __syncthreads();
    for (int d = 1; d < 256; d <<= 1) {
        int x = (t >= d) ? sm[t - d] : 0;
        __syncthreads();
        sm[t] += x;
        __syncthreads();
    }
    int excl = sm[t] - v + g_boff[b];
    if (n < NN) {
        g_off[n] = excl;
        g_cur[n] = excl;
    }
    if (b == 0 && t == 0) g_off[NN] = EE;
}

// ---------------- K4: GEMM1  h1s = dinv*(x@Wi), root1 = x@Wr ----------------
// tile: 128 nodes x 64 outputs, 256 threads; thread = 8 rows x 4 cols (f32x2)
__global__ void __launch_bounds__(256) k_gemm1(const float* __restrict__ x,
                                               const float* __restrict__ wi,
                                               const float* __restrict__ wr) {
    __shared__ float xs[128 * 68];
    __shared__ float ws[64 * 64];
    int tid = threadIdx.x;
    int nb = blockIdx.x * 128;
    int co = tid & 15;   // output group: cols co*4 .. co*4+3
    int rn = tid >> 4;   // row group:    rows rn*8 .. rn*8+7

    unsigned long long acc[8][2];
#pragma unroll
    for (int i = 0; i < 8; i++) { acc[i][0] = 0ull; acc[i][1] = 0ull; }

    for (int fc = 0; fc < 256; fc += 64) {
        // stage x tile [128 rows x 64 features], 8 float4/thread
#pragma unroll
        for (int j = 0; j < 8; j++) {
            int idx = tid + 256 * j;
            int r = idx >> 4;
            int c4 = (idx & 15) * 4;
            float4 v = make_float4(0.f, 0.f, 0.f, 0.f);
            int node = nb + r;
            if (node < NN) v = *(const float4*)&x[node * 256 + fc + c4];
            *(float4*)&xs[r * 68 + c4] = v;
        }
        // stage W tile [64 f x 64 outputs], 4 float4/thread
        // o layout: [wi k0 h0..15 | wi k1 h0..15 | wr k0 h0..15 | wr k1 h0..15]
#pragma unroll
        for (int j = 0; j < 4; j++) {
            int idx = tid + 256 * j;
            int fl = idx >> 4;
            int o4 = idx & 15;
            int m = o4 >> 2;      // 0..3
            int k = m & 1;
            int h4 = o4 & 3;
            const float* wp = (m < 2) ? wi : wr;
            float4 v = *(const float4*)&wp[k * 4096 + (fc + fl) * 16 + h4 * 4];
            *(float4*)&ws[fl * 64 + o4 * 4] = v;
        }
        __syncthreads();
#pragma unroll 8
        for (int f = 0; f < 64; f++) {
            float4 w = *(float4*)&ws[f * 64 + co * 4];
            unsigned long long w01 = pack2(w.x, w.y);
            unsigned long long w23 = pack2(w.z, w.w);
#pragma unroll
            for (int i = 0; i < 8; i++) {
                float xv = xs[(rn * 8 + i) * 68 + f];
                unsigned long long xx = pack2(xv, xv);
                acc[i][0] = ffma2(xx, w01, acc[i][0]);
                acc[i][1] = ffma2(xx, w23, acc[i][1]);
            }
        }
        __syncthreads();
    }
    // epilogue
#pragma unroll
    for (int i = 0; i < 8; i++) {
        int node = nb + rn * 8 + i;
        if (node >= NN) continue;
        float4 v;
        unpack2(acc[i][0], v.x, v.y);
        unpack2(acc[i][1], v.z, v.w);
        if (co < 8) {
            float dv = g_dinv[node];
            v.x *= dv; v.y *= dv; v.z *= dv; v.w *= dv;
            *(float4*)&g_h1s[node * 32 + co * 4] = v;
        } else {
            *(float4*)&g_root1[node * 32 + (co - 8) * 4] = v;
        }
    }
}

// ---------------- K5: CSR scatter (src grouped by dst), int4 vectorized -----
__global__ void k_csr(const int* __restrict__ ei) {
    int e4 = blockIdx.x * blockDim.x + threadIdx.x;
    if (e4 >= EE / 4) return;
    int4 s = *(const int4*)&ei[e4 * 4];
    int4 d = *(const int4*)&ei[EE + e4 * 4];
    if ((unsigned)d.x < NN) g_csrc[atomicAdd(&g_cur[d.x], 1)] = s.x;
    if ((unsigned)d.y < NN) g_csrc[atomicAdd(&g_cur[d.y], 1)] = s.y;
    if ((unsigned)d.z < NN) g_csrc[atomicAdd(&g_cur[d.z], 1)] = s.z;
    if ((unsigned)d.w < NN) g_csrc[atomicAdd(&g_cur[d.w], 1)] = s.w;
}

// ---------------- K6: layer-1 aggregate + combine ----------------------------
// warp per dst node; 8 lanes cover one 128B row; 4 neighbors in flight
__global__ void __launch_bounds__(256) k_agg1(const float* __restrict__ bias1,
                                              float* __restrict__ out_agg) {
    int node = blockIdx.x * 8 + (threadIdx.x >> 5);
    int lane = threadIdx.x & 31;
    if (node >= NN) return;
    int beg = g_off[node], end = g_off[node + 1];
    int grp = lane >> 3;       // 0..3: which neighbor in the 4-batch
    int cb = (lane & 7) * 4;   // column base 0..28

    float4 acc = make_float4(0.f, 0.f, 0.f, 0.f);
    for (int t = beg; t < end; t += 32) {
        int idx = t + lane;
        int sv = (idx < end) ? g_csrc[idx] : 0;
        int cnt = min(32, end - t);
        for (int j = 0; j < cnt; j += 4) {
            int jj = j + grp;
            int s = __shfl_sync(0xffffffffu, sv, jj & 31);
            if (jj < cnt) {
                float4 a = *(const float4*)&g_h1s[s * 32 + cb];
                acc.x += a.x; acc.y += a.y; acc.z += a.z; acc.w += a.w;
            }
        }
    }
    // reduce across the 4 neighbor groups (lane bits 3,4)
#pragma unroll
    for (int m = 8; m <= 16; m <<= 1) {
        acc.x += __shfl_xor_sync(0xffffffffu, acc.x, m);
        acc.y += __shfl_xor_sync(0xffffffffu, acc.y, m);
        acc.z += __shfl_xor_sync(0xffffffffu, acc.z, m);
        acc.w += __shfl_xor_sync(0xffffffffu, acc.w, m);
    }
    // lanes 0..7 hold full col sums for cols cb..cb+3
    float dv = g_dinv[node];
    float4 root = *(const float4*)&g_root1[node * 32 + cb];
    float4 bv = *(const float4*)&bias1[cb];
    float4 r;
    r.x = fmaxf(dv * acc.x + root.x + bv.x, 0.f);
    r.y = fmaxf(dv * acc.y + root.y + bv.y, 0.f);
    r.z = fmaxf(dv * acc.z + root.z + bv.z, 0.f);
    r.w = fmaxf(dv * acc.w + root.w + bv.w, 0.f);
    // K-mean: col c pairs with c+16 -> lane pairs with lane^4
    float4 o;
    o.x = __shfl_xor_sync(0xffffffffu, r.x, 4);
    o.y = __shfl_xor_sync(0xffffffffu, r.y, 4);
    o.z = __shfl_xor_sync(0xffffffffu, r.z, 4);
    o.w = __shfl_xor_sync(0xffffffffu, r.w, 4);
    float4 h;
    h.x = 0.5f * (r.x + o.x);
    h.y = 0.5f * (r.y + o.y);
    h.z = 0.5f * (r.z + o.z);
    h.w = 0.5f * (r.w + o.w);
    if (lane < 4) {
        *(float4*)&out_agg[node * 16 + lane * 4] = h;   // agg_feature output
        float4 hs = make_float4(h.x * dv, h.y * dv, h.z * dv, h.w * dv);
        *(float4*)&g_hs[node * 16 + lane * 4] = hs;
    }
}

// ---------------- K7: layer-2 aggregate --------------------------------------
// warp per dst node; 4 lanes cover one 64B row; 8 neighbors in flight
__global__ void __launch_bounds__(256) k_agg2() {
    int node = blockIdx.x * 8 + (threadIdx.x >> 5);
    int lane = threadIdx.x & 31;
    if (node >= NN) return;
    int beg = g_off[node], end = g_off[node + 1];
    int grp = lane >> 2;       // 0..7
    int cb = (lane & 3) * 4;   // column base 0..12

    float4 acc = make_float4(0.f, 0.f, 0.f, 0.f);
    for (int t = beg; t < end; t += 32) {
        int idx = t + lane;
        int sv = (idx < end) ? g_csrc[idx] : 0;
        int cnt = min(32, end - t);
        for (int j = 0; j < cnt; j += 8) {
            int jj = j + grp;
            int s = __shfl_sync(0xffffffffu, sv, jj & 31);
            if (jj < cnt) {
                float4 a = *(const float4*)&g_hs[s * 16 + cb];
                acc.x += a.x; acc.y += a.y; acc.z += a.z; acc.w += a.w;
            }
        }
    }
#pragma unroll
    for (int m = 4; m <= 16; m <<= 1) {
        acc.x += __shfl_xor_sync(0xffffffffu, acc.x, m);
        acc.y += __shfl_xor_sync(0xffffffffu, acc.y, m);
        acc.z += __shfl_xor_sync(0xffffffffu, acc.z, m);
        acc.w += __shfl_xor_sync(0xffffffffu, acc.w, m);
    }
    if (lane < 4) {
        float dv = g_dinv[node];
        float4 v = make_float4(acc.x * dv, acc.y * dv, acc.z * dv, acc.w * dv);
        *(float4*)&g_aggh[node * 16 + lane * 4] = v;
    }
}

// ---------------- K8: layer-2 transform + log_softmax ------------------------
__global__ void __launch_bounds__(256) k_final(const float* __restrict__ wi2,
                                               const float* __restrict__ wr2,
                                               const float* __restrict__ b2,
                                               const float* __restrict__ hsrc,
                                               float* __restrict__ out_logits) {
    __shared__ float Wi[256], Wr[256], Ba[16];
    int t = threadIdx.x;
    // K-mean commutes with identity activation -> average weights over stacks
    Wi[t] = 0.5f * (wi2[t] + wi2[256 + t]);
    Wr[t] = 0.5f * (wr2[t] + wr2[256 + t]);
    if (t < 16) Ba[t] = 0.5f * (b2[t] + b2[16 + t]);
    __syncthreads();

    int n = blockIdx.x * 256 + t;
    if (n >= NN) return;
    float g[16], h[16];
#pragma unroll
    for (int j = 0; j < 4; j++) {
        float4 gv = *(const float4*)&g_aggh[n * 16 + j * 4];
        float4 hv = *(const float4*)&hsrc[n * 16 + j * 4];
        g[j * 4 + 0] = gv.x; g[j * 4 + 1] = gv.y; g[j * 4 + 2] = gv.z; g[j * 4 + 3] = gv.w;
        h[j * 4 + 0] = hv.x; h[j * 4 + 1] = hv.y; h[j * 4 + 2] = hv.z; h[j * 4 + 3] = hv.w;
    }
    float l[16];
    float m = -1e30f;
#pragma unroll
    for (int o = 0; o < 16; o++) {
        float a = Ba[o];
#pragma unroll
        for (int ff = 0; ff < 16; ff++)
            a += g[ff] * Wi[ff * 16 + o] + h[ff] * Wr[ff * 16 + o];
        l[o] = a;
        m = fmaxf(m, a);
    }
    float s = 0.f;
#pragma unroll
    for (int o = 0; o < 16; o++) s += expf(l[o] - m);
    float ls = logf(s);
#pragma unroll
    for (int j = 0; j < 4; j++) {
        float4 v;
        v.x = l[j * 4 + 0] - m - ls;
        v.y = l[j * 4 + 1] - m - ls;
        v.z = l[j * 4 + 2] - m - ls;
        v.w = l[j * 4 + 3] - m - ls;
        *(float4*)&out_logits[n * 16 + j * 4] = v;
    }
}

// ---------------- launch -----------------------------------------------------
extern "C" void kernel_launch(void* const* d_in, const int* in_sizes, int n_in,
                              void* d_out, int out_size) {
    const float* x   = (const float*)d_in[0];
    const int*   ei  = (const int*)d_in[1];     // int32 (JAX x64 disabled)
    const float* wi1 = (const float*)d_in[2];
    const float* wr1 = (const float*)d_in[3];
    const float* b1  = (const float*)d_in[4];
    const float* wi2 = (const float*)d_in[5];
    const float* wr2 = (const float*)d_in[6];
    const float* b2  = (const float*)d_in[7];
    float* out        = (float*)d_out;
    float* out_logits = out;            // [N, 16] log_softmax
    float* out_agg    = out + NN * 16;  // [N, 16] agg_feature

    k_zero<<<(NN + 255) / 256, 256>>>();                 // 1
    k_hist<<<(EE / 4 + 255) / 256, 256>>>(ei);           // 2
    k_scan_part<<<NB_SCAN, 256>>>();                     // 3 (+dinv)
    k_scan_top<<<1, 512>>>();                            // 4
    k_scan_out<<<NB_SCAN, 256>>>();                      // 5
    k_gemm1<<<(NN + 127) / 128, 256>>>(x, wi1, wr1);     // 6  <- ncu profiles this
    k_csr<<<(EE / 4 + 255) / 256, 256>>>(ei);            // 7
    k_agg1<<<(NN + 7) / 8, 256>>>(b1, out_agg);          // 8
    k_agg2<<<(NN + 7) / 8, 256>>>();                     // 9
    k_final<<<(NN + 255) / 256, 256>>>(wi2, wr2, b2, out_agg, out_logits);  // 10
}

// round 4
// speedup vs baseline: 1.3468x; 1.1021x over previous
#include <cuda_runtime.h>

#define NN  100000
#define EE  3200000
#define NB_SCAN 391   // ceil(NN/256)

// ---------------- scratch (static device globals) ---------------------------
__device__ int   g_degi[NN];
__device__ float g_dinv[NN];
__device__ int   g_off[NN + 1];
__device__ int   g_cur[NN];
__device__ int   g_csrc[EE];
__device__ float g_h1s[NN * 32];    // x[n] @ init_w1 (raw), cols = k*16+h
__device__ float g_root1[NN * 32];  // x[n] @ root_w1 (raw)
__device__ float g_hs[NN * 16];     // dinv[n] * h[n]
__device__ float g_aggh[NN * 16];   // dinv[d] * sum_src hs[src]
__device__ int   g_bsum[512];
__device__ int   g_boff[512];

// ---------------- streams/events (created at image load, before harness) ----
struct HxStreams {
    cudaStream_t s2 = nullptr;
    cudaEvent_t ev_fork = nullptr, ev_join = nullptr;
    bool ok = false;
    HxStreams() {
        ok = (cudaStreamCreateWithFlags(&s2, cudaStreamNonBlocking) == cudaSuccess) &&
             (cudaEventCreateWithFlags(&ev_fork, cudaEventDisableTiming) == cudaSuccess) &&
             (cudaEventCreateWithFlags(&ev_join, cudaEventDisableTiming) == cudaSuccess);
    }
};
static HxStreams g_hx;

// ---------------- packed f32x2 helpers ---------------------------------------
__device__ __forceinline__ unsigned long long ffma2(unsigned long long a,
                                                    unsigned long long b,
                                                    unsigned long long c) {
    unsigned long long d;
    asm("fma.rn.f32x2 %0, %1, %2, %3;" : "=l"(d) : "l"(a), "l"(b), "l"(c));
    return d;
}
__device__ __forceinline__ unsigned long long pack2(float lo, float hi) {
    unsigned long long r;
    asm("mov.b64 %0, {%1, %2};" : "=l"(r) : "f"(lo), "f"(hi));
    return r;
}
__device__ __forceinline__ void unpack2(unsigned long long v, float& lo, float& hi) {
    asm("mov.b64 {%0, %1}, %2;" : "=f"(lo), "=f"(hi) : "l"(v));
}

// ---------------- K: zero degree histogram -----------------------------------
__global__ void k_zero() {
    int i = blockIdx.x * blockDim.x + threadIdx.x;
    if (i < NN) g_degi[i] = 0;
}

// ---------------- K: degree histogram (int32 dst, int4 vectorized) ----------
__global__ void k_hist(const int* __restrict__ ei) {
    int e4 = blockIdx.x * blockDim.x + threadIdx.x;
    if (e4 >= EE / 4) return;
    int4 d = *(const int4*)&ei[EE + e4 * 4];
    if ((unsigned)d.x < NN) atomicAdd(&g_degi[d.x], 1);
    if ((unsigned)d.y < NN) atomicAdd(&g_degi[d.y], 1);
    if ((unsigned)d.z < NN) atomicAdd(&g_degi[d.z], 1);
    if ((unsigned)d.w < NN) atomicAdd(&g_degi[d.w], 1);
}

// ---------------- scan partials + dinv ---------------------------------------
__global__ void k_scan_part() {
    __shared__ int sm[256];
    int t = threadIdx.x, b = blockIdx.x;
    int n = b * 256 + t;
    int v = (n < NN) ? g_degi[n] : 0;
    if (n < NN) g_dinv[n] = (v > 0) ? rsqrtf((float)v) : 0.0f;
    sm[t] = v;
    __syncthreads();
    for (int s = 128; s > 0; s >>= 1) {
        if (t < s) sm[t] += sm[t + s];
        __syncthreads();
    }
    if (t == 0) g_bsum[b] = sm[0];
}

__global__ void k_scan_top() {
    __shared__ int sm[512];
    int t = threadIdx.x;
    int v = (t < NB_SCAN) ? g_bsum[t] : 0;
    sm[t] = v;
    __syncthreads();
    for (int d = 1; d < 512; d <<= 1) {
        int x = (t >= d) ? sm[t - d] : 0;
        __syncthreads();
        sm[t] += x;
        __syncthreads();
    }
    if (t < NB_SCAN) g_boff[t] = sm[t] - v;  // exclusive
}

__global__ void k_scan_out() {
    __shared__ int sm[256];
    int t = threadIdx.x, b = blockIdx.x;
    int n = b * 256 + t;
    int v = (n < NN) ? g_degi[n] : 0;
    sm[t] = v;
    __syncthreads();
    for (int d = 1; d < 256; d <<= 1) {
        int x = (t >= d) ? sm[t - d] : 0;
        __syncthreads();
        sm[t] += x;
        __syncthreads();
    }
    int excl = sm[t] - v + g_boff[b];
    if (n < NN) {
        g_off[n] = excl;
        g_cur[n] = excl;
    }
    if (b == 0 && t == 0) g_off[NN] = EE;
}

// ---------------- GEMM1  h1s = x@Wi, root1 = x@Wr (raw, no dinv) ------------
// tile: 128 rows x 64 outs; 256 thr; thread = 4 row-pairs x 4 cols via FFMA2
#define XPAD 130
__global__ void __launch_bounds__(256) k_gemm1(const float* __restrict__ x,
                                               const float* __restrict__ wi,
                                               const float* __restrict__ wr) {
    __shared__ float xs[32 * XPAD];   // column-major: xs[f*XPAD + r]
    __shared__ float ws[32 * 64];
    int tid = threadIdx.x;
    int nb = blockIdx.x * 128;
    int co = tid & 15;   // cols co*4 .. co*4+3
    int rn = tid >> 4;   // rows rn*8 .. rn*8+7 (4 pairs)

    unsigned long long acc[4][4];
#pragma unroll
    for (int i = 0; i < 4; i++)
#pragma unroll
        for (int c = 0; c < 4; c++) acc[i][c] = 0ull;

    for (int fc = 0; fc < 256; fc += 32) {
        // stage x tile [128 rows x 32 f] into column-major xs
#pragma unroll
        for (int j = 0; j < 4; j++) {
            int idx = tid + 256 * j;        // 1024 float4 slots
            int r = idx >> 3;               // row 0..127
            int c4 = (idx & 7) * 4;         // f 0..28
            float4 v = make_float4(0.f, 0.f, 0.f, 0.f);
            int node = nb + r;
            if (node < NN) v = *(const float4*)&x[node * 256 + fc + c4];
            xs[(c4 + 0) * XPAD + r] = v.x;
            xs[(c4 + 1) * XPAD + r] = v.y;
            xs[(c4 + 2) * XPAD + r] = v.z;
            xs[(c4 + 3) * XPAD + r] = v.w;
        }
        // stage W tile [32 f x 64 outs]
        // o layout: [wi k0 h0..15 | wi k1 h0..15 | wr k0 h0..15 | wr k1 h0..15]
#pragma unroll
        for (int j = 0; j < 2; j++) {
            int idx = tid + 256 * j;
            int fl = idx >> 4;
            int o4 = idx & 15;
            int m = o4 >> 2;
            int k = m & 1;
            int h4 = o4 & 3;
            const float* wp = (m < 2) ? wi : wr;
            float4 v = *(const float4*)&wp[k * 4096 + (fc + fl) * 16 + h4 * 4];
            *(float4*)&ws[fl * 64 + o4 * 4] = v;
        }
        __syncthreads();
#pragma unroll 8
        for (int f = 0; f < 32; f++) {
            float4 w = *(float4*)&ws[f * 64 + co * 4];
            unsigned long long wx = pack2(w.x, w.x);
            unsigned long long wy = pack2(w.y, w.y);
            unsigned long long wz = pack2(w.z, w.z);
            unsigned long long ww = pack2(w.w, w.w);
#pragma unroll
            for (int i = 0; i < 4; i++) {
                float2 xr = *(float2*)&xs[f * XPAD + rn * 8 + i * 2];
                unsigned long long xp = pack2(xr.x, xr.y);
                acc[i][0] = ffma2(xp, wx, acc[i][0]);
                acc[i][1] = ffma2(xp, wy, acc[i][1]);
                acc[i][2] = ffma2(xp, wz, acc[i][2]);
                acc[i][3] = ffma2(xp, ww, acc[i][3]);
            }
        }
        __syncthreads();
    }
    // epilogue: each pair i holds rows rn*8+2i (lo) and rn*8+2i+1 (hi)
#pragma unroll
    for (int i = 0; i < 4; i++) {
        float4 va, vb;
        unpack2(acc[i][0], va.x, vb.x);
        unpack2(acc[i][1], va.y, vb.y);
        unpack2(acc[i][2], va.z, vb.z);
        unpack2(acc[i][3], va.w, vb.w);
        int ra = nb + rn * 8 + 2 * i;
        int rb = ra + 1;
        if (ra < NN) {
            if (co < 8) *(float4*)&g_h1s[ra * 32 + co * 4] = va;
            else        *(float4*)&g_root1[ra * 32 + (co - 8) * 4] = va;
        }
        if (rb < NN) {
            if (co < 8) *(float4*)&g_h1s[rb * 32 + co * 4] = vb;
            else        *(float4*)&g_root1[rb * 32 + (co - 8) * 4] = vb;
        }
    }
}

// ---------------- CSR scatter (src grouped by dst), int4 vectorized ---------
__global__ void k_csr(const int* __restrict__ ei) {
    int e4 = blockIdx.x * blockDim.x + threadIdx.x;
    if (e4 >= EE / 4) return;
    int4 s = *(const int4*)&ei[e4 * 4];
    int4 d = *(const int4*)&ei[EE + e4 * 4];
    if ((unsigned)d.x < NN) g_csrc[atomicAdd(&g_cur[d.x], 1)] = s.x;
    if ((unsigned)d.y < NN) g_csrc[atomicAdd(&g_cur[d.y], 1)] = s.y;
    if ((unsigned)d.z < NN) g_csrc[atomicAdd(&g_cur[d.z], 1)] = s.z;
    if ((unsigned)d.w < NN) g_csrc[atomicAdd(&g_cur[d.w], 1)] = s.w;
}

// ---------------- layer-1 aggregate + combine (dinv[src] applied here) ------
// warp per dst node; 8 lanes cover one 128B row; 4 neighbors in flight
__global__ void __launch_bounds__(256) k_agg1(const float* __restrict__ bias1,
                                              float* __restrict__ out_agg) {
    int node = blockIdx.x * 8 + (threadIdx.x >> 5);
    int lane = threadIdx.x & 31;
    if (node >= NN) return;
    int beg = g_off[node], end = g_off[node + 1];
    int grp = lane >> 3;       // 0..3: which neighbor in the 4-batch
    int cb = (lane & 7) * 4;   // column base 0..28

    float4 acc = make_float4(0.f, 0.f, 0.f, 0.f);
    for (int t = beg; t < end; t += 32) {
        int idx = t + lane;
        int sv = (idx < end) ? g_csrc[idx] : 0;
        int cnt = min(32, end - t);
        for (int j = 0; j < cnt; j += 4) {
            int jj = j + grp;
            int s = __shfl_sync(0xffffffffu, sv, jj & 31);
            if (jj < cnt) {
                float dvs = g_dinv[s];
                float4 a = *(const float4*)&g_h1s[s * 32 + cb];
                acc.x = fmaf(a.x, dvs, acc.x);
                acc.y = fmaf(a.y, dvs, acc.y);
                acc.z = fmaf(a.z, dvs, acc.z);
                acc.w = fmaf(a.w, dvs, acc.w);
            }
        }
    }
    // reduce across the 4 neighbor groups (lane bits 3,4)
#pragma unroll
    for (int m = 8; m <= 16; m <<= 1) {
        acc.x += __shfl_xor_sync(0xffffffffu, acc.x, m);
        acc.y += __shfl_xor_sync(0xffffffffu, acc.y, m);
        acc.z += __shfl_xor_sync(0xffffffffu, acc.z, m);
        acc.w += __shfl_xor_sync(0xffffffffu, acc.w, m);
    }
    // lanes 0..7 hold full col sums for cols cb..cb+3
    float dv = g_dinv[node];
    float4 root = *(const float4*)&g_root1[node * 32 + cb];
    float4 bv = *(const float4*)&bias1[cb];
    float4 r;
    r.x = fmaxf(dv * acc.x + root.x + bv.x, 0.f);
    r.y = fmaxf(dv * acc.y + root.y + bv.y, 0.f);
    r.z = fmaxf(dv * acc.z + root.z + bv.z, 0.f);
    r.w = fmaxf(dv * acc.w + root.w + bv.w, 0.f);
    // K-mean: col c pairs with c+16 -> lane pairs with lane^4
    float4 o;
    o.x = __shfl_xor_sync(0xffffffffu, r.x, 4);
    o.y = __shfl_xor_sync(0xffffffffu, r.y, 4);
    o.z = __shfl_xor_sync(0xffffffffu, r.z, 4);
    o.w = __shfl_xor_sync(0xffffffffu, r.w, 4);
    float4 h;
    h.x = 0.5f * (r.x + o.x);
    h.y = 0.5f * (r.y + o.y);
    h.z = 0.5f * (r.z + o.z);
    h.w = 0.5f * (r.w + o.w);
    if (lane < 4) {
        *(float4*)&out_agg[node * 16 + lane * 4] = h;   // agg_feature output
        float4 hs = make_float4(h.x * dv, h.y * dv, h.z * dv, h.w * dv);
        *(float4*)&g_hs[node * 16 + lane * 4] = hs;
    }
}

// ---------------- layer-2 aggregate ------------------------------------------
// warp per dst node; 4 lanes cover one 64B row; 8 neighbors in flight
__global__ void __launch_bounds__(256) k_agg2() {
    int node = blockIdx.x * 8 + (threadIdx.x >> 5);
    int lane = threadIdx.x & 31;
    if (node >= NN) return;
    int beg = g_off[node], end = g_off[node + 1];
    int grp = lane >> 2;       // 0..7
    int cb = (lane & 3) * 4;   // column base 0..12

    float4 acc = make_float4(0.f, 0.f, 0.f, 0.f);
    for (int t = beg; t < end; t += 32) {
        int idx = t + lane;
        int sv = (idx < end) ? g_csrc[idx] : 0;
        int cnt = min(32, end - t);
        for (int j = 0; j < cnt; j += 8) {
            int jj = j + grp;
            int s = __shfl_sync(0xffffffffu, sv, jj & 31);
            if (jj < cnt) {
                float4 a = *(const float4*)&g_hs[s * 16 + cb];
                acc.x += a.x; acc.y += a.y; acc.z += a.z; acc.w += a.w;
            }
        }
    }
#pragma unroll
    for (int m = 4; m <= 16; m <<= 1) {
        acc.x += __shfl_xor_sync(0xffffffffu, acc.x, m);
        acc.y += __shfl_xor_sync(0xffffffffu, acc.y, m);
        acc.z += __shfl_xor_sync(0xffffffffu, acc.z, m);
        acc.w += __shfl_xor_sync(0xffffffffu, acc.w, m);
    }
    if (lane < 4) {
        float dv = g_dinv[node];
        float4 v = make_float4(acc.x * dv, acc.y * dv, acc.z * dv, acc.w * dv);
        *(float4*)&g_aggh[node * 16 + lane * 4] = v;
    }
}

// ---------------- layer-2 transform + log_softmax ----------------------------
__global__ void __launch_bounds__(256) k_final(const float* __restrict__ wi2,
                                               const float* __restrict__ wr2,
                                               const float* __restrict__ b2,
                                               const float* __restrict__ hsrc,
                                               float* __restrict__ out_logits) {
    __shared__ float Wi[256], Wr[256], Ba[16];
    int t = threadIdx.x;
    // K-mean commutes with identity activation -> average weights over stacks
    Wi[t] = 0.5f * (wi2[t] + wi2[256 + t]);
    Wr[t] = 0.5f * (wr2[t] + wr2[256 + t]);
    if (t < 16) Ba[t] = 0.5f * (b2[t] + b2[16 + t]);
    __syncthreads();

    int n = blockIdx.x * 256 + t;
    if (n >= NN) return;
    float g[16], h[16];
#pragma unroll
    for (int j = 0; j < 4; j++) {
        float4 gv = *(const float4*)&g_aggh[n * 16 + j * 4];
        float4 hv = *(const float4*)&hsrc[n * 16 + j * 4];
        g[j * 4 + 0] = gv.x; g[j * 4 + 1] = gv.y; g[j * 4 + 2] = gv.z; g[j * 4 + 3] = gv.w;
        h[j * 4 + 0] = hv.x; h[j * 4 + 1] = hv.y; h[j * 4 + 2] = hv.z; h[j * 4 + 3] = hv.w;
    }
    float l[16];
    float m = -1e30f;
#pragma unroll
    for (int o = 0; o < 16; o++) {
        float a = Ba[o];
#pragma unroll
        for (int ff = 0; ff < 16; ff++)
            a += g[ff] * Wi[ff * 16 + o] + h[ff] * Wr[ff * 16 + o];
        l[o] = a;
        m = fmaxf(m, a);
    }
    float s = 0.f;
#pragma unroll
    for (int o = 0; o < 16; o++) s += expf(l[o] - m);
    float ls = logf(s);
#pragma unroll
    for (int j = 0; j < 4; j++) {
        float4 v;
        v.x = l[j * 4 + 0] - m - ls;
        v.y = l[j * 4 + 1] - m - ls;
        v.z = l[j * 4 + 2] - m - ls;
        v.w = l[j * 4 + 3] - m - ls;
        *(float4*)&out_logits[n * 16 + j * 4] = v;
    }
}

// ---------------- launch -----------------------------------------------------
extern "C" void kernel_launch(void* const* d_in, const int* in_sizes, int n_in,
                              void* d_out, int out_size) {
    const float* x   = (const float*)d_in[0];
    const int*   ei  = (const int*)d_in[1];     // int32 (JAX x64 disabled)
    const float* wi1 = (const float*)d_in[2];
    const float* wr1 = (const float*)d_in[3];
    const float* b1  = (const float*)d_in[4];
    const float* wi2 = (const float*)d_in[5];
    const float* wr2 = (const float*)d_in[6];
    const float* b2  = (const float*)d_in[7];
    float* out        = (float*)d_out;
    float* out_logits = out;            // [N, 16] log_softmax
    float* out_agg    = out + NN * 16;  // [N, 16] agg_feature

    bool dual = g_hx.ok;
    if (dual) cudaEventRecord(g_hx.ev_fork, 0);   // fork point: t ~ 0

    // main stream: CSR build chain
    k_zero<<<(NN + 255) / 256, 256>>>();
    k_hist<<<(EE / 4 + 255) / 256, 256>>>(ei);
    k_scan_part<<<NB_SCAN, 256>>>();

    // gemm1: independent of everything; overlaps the CSR chain on s2
    if (dual) {
        cudaStreamWaitEvent(g_hx.s2, g_hx.ev_fork, 0);
        k_gemm1<<<(NN + 127) / 128, 256, 0, g_hx.s2>>>(x, wi1, wr1);  // 4th launch
        cudaEventRecord(g_hx.ev_join, g_hx.s2);
    } else {
        k_gemm1<<<(NN + 127) / 128, 256>>>(x, wi1, wr1);
    }

    k_scan_top<<<1, 512>>>();
    k_scan_out<<<NB_SCAN, 256>>>();
    k_csr<<<(EE / 4 + 255) / 256, 256>>>(ei);

    if (dual) cudaStreamWaitEvent(0, g_hx.ev_join, 0);  // join before agg1

    k_agg1<<<(NN + 7) / 8, 256>>>(b1, out_agg);
    k_agg2<<<(NN + 7) / 8, 256>>>();
    k_final<<<(NN + 255) / 256, 256>>>(wi2, wr2, b2, out_agg, out_logits);
}